// round 12
// baseline (speedup 1.0000x reference)
#include <cuda_runtime.h>
#include <cuda_fp16.h>
#include <math.h>
#include <stdint.h>

#define Bn 2
#define Sn 2048
#define Dn 1024
#define Hn 16
#define HDn 64
#define BSn (Bn*Sn)      // 4096
#define N3D (3*Dn)       // 3072
#define NQKV (Bn*Hn*Sn*HDn)

// wide stage (128m x 128n, k64): Ah 16KB | Al 16KB | B 16KB = 48KB
#define SLOT_W  49152
#define SMEM_W  (2*SLOT_W)    // 98304 -> 2 CTAs/SM
#define SMEM_SC SLOT_W        // scores single-shot K=64
// av_fused k32 slot: raw fp32 A 16KB | Bh 4KB | Bl 4KB = 24KB
#define AV_SLOT 24576
#define AV_A16  (2*AV_SLOT)           // fp16 A region, 128 rows x 64B = 8KB
#define AV_STATS (AV_A16 + 8192)      // 128 m + 128 inv_s
#define SMEM_AVF (AV_STATS + 1024)    // 58368 -> 3 CTAs/SM

// ---------------- fp16 scratch (device globals) ----------------
__device__ __half s_hs_h[BSn*Dn],  s_hs_l[BSn*Dn];   // hidden states split
__device__ __half s_wa_h[N3D*Dn];                    // w_attn^T single
__device__ __half s_wp_h[Dn*Dn];                     // w_proj^T single
__device__ __half g_q_h[NQKV], g_q_l[NQKV];          // q split   [bh][s][hd]
__device__ __half g_k_h[NQKV];                       // k single  [bh][s][hd]
__device__ __half g_v_h[NQKV], g_v_l[NQKV];          // v split   [bh][hd][s]
__device__ __half g_att_h[NQKV], g_att_l[NQKV];      // att split [bh][s][hd]

// ---------------- helpers ----------------
__device__ __forceinline__ uint32_t s2u(const void* p) {
    return (uint32_t)__cvta_generic_to_shared(p);
}
__device__ __forceinline__ void ldsm4(uint32_t& r0, uint32_t& r1, uint32_t& r2,
                                      uint32_t& r3, uint32_t a) {
    asm volatile("ldmatrix.sync.aligned.m8n8.x4.shared.b16 {%0,%1,%2,%3},[%4];"
                 : "=r"(r0), "=r"(r1), "=r"(r2), "=r"(r3) : "r"(a));
}
#define MMAF(c, a, b) asm volatile( \
    "mma.sync.aligned.m16n8k16.row.col.f32.f16.f16.f32 " \
    "{%0,%1,%2,%3},{%4,%5,%6,%7},{%8,%9},{%0,%1,%2,%3};" \
    : "+f"((c)[0]), "+f"((c)[1]), "+f"((c)[2]), "+f"((c)[3]) \
    : "r"((a)[0]), "r"((a)[1]), "r"((a)[2]), "r"((a)[3]), "r"((b)[0]), "r"((b)[1]))

__device__ __forceinline__ void cpa16(uint32_t dst, const void* src) {
    asm volatile("cp.async.cg.shared.global [%0], [%1], 16;" :: "r"(dst), "l"(src));
}
#define CP_COMMIT() asm volatile("cp.async.commit_group;")
#define CP_WAIT0()  asm volatile("cp.async.wait_group 0;")

// 16B chunk c (0..7) in swizzled 128B row
__device__ __forceinline__ uint32_t swz(int row, int c) {
    return (uint32_t)row * 128u + (uint32_t)((c ^ (row & 7)) << 4);
}
// 16B chunk c (0..3) in swizzled 64B row
__device__ __forceinline__ uint32_t swz64(int row, int c) {
    return (uint32_t)row * 64u + (uint32_t)((c ^ (row & 3)) << 4);
}

__device__ __forceinline__ void split2(float x, float y, uint32_t& ph, uint32_t& pl) {
    __half2 h2 = __floats2half2_rn(x, y);
    ph = *reinterpret_cast<uint32_t*>(&h2);
    __half2 l2 = __floats2half2_rn(x - __half2float(__low2half(h2)),
                                   y - __half2float(__high2half(h2)));
    pl = *reinterpret_cast<uint32_t*>(&l2);
}
__device__ __forceinline__ uint32_t pack2(float x, float y) {
    __half2 h2 = __floats2half2_rn(x, y);
    return *reinterpret_cast<uint32_t*>(&h2);
}

// wide stage (k64): split A (Ah @0, Al @16384), single B (@32768, 128 rows).
// warp grid 2m x 4n: warp tile 64m x 32n; acc[4][4][4].
__device__ __forceinline__ void cstage_w(uint32_t sb, float acc[4][4][4],
                                         int mbase, int nbase, int lane) {
    #pragma unroll
    for (int kk = 0; kk < 4; kk++) {
        uint32_t bf[4][2];
        #pragma unroll
        for (int jg = 0; jg < 2; jg++) {
            int brow = nbase + jg * 16 + (lane & 7) + ((lane >> 4) << 3);
            int bch = kk * 2 + ((lane >> 3) & 1);
            uint32_t r0, r1, r2, r3;
            ldsm4(r0, r1, r2, r3, sb + 32768u + swz(brow, bch));
            bf[jg * 2][0] = r0; bf[jg * 2][1] = r1;
            bf[jg * 2 + 1][0] = r2; bf[jg * 2 + 1][1] = r3;
        }
        #pragma unroll
        for (int i = 0; i < 4; i++) {
            int arow = mbase + i * 16 + (lane & 15);
            int ach = kk * 2 + (lane >> 4);
            uint32_t ah[4], al[4];
            ldsm4(ah[0], ah[1], ah[2], ah[3], sb + swz(arow, ach));
            ldsm4(al[0], al[1], al[2], al[3], sb + 16384u + swz(arow, ach));
            #pragma unroll
            for (int j = 0; j < 4; j++) {
                MMAF(acc[i][j], ah, bf[j]);
                MMAF(acc[i][j], al, bf[j]);
            }
        }
    }
}

// ---------------------------------------------------------------------------
// Kernel 0a: split hidden states.
// ---------------------------------------------------------------------------
__global__ __launch_bounds__(256) void split_hs(const float* __restrict__ hs) {
    int i = (blockIdx.x * 256 + threadIdx.x) * 4;
    float4 v = *(const float4*)&hs[i];
    uint32_t ph0, pl0, ph1, pl1;
    split2(v.x, v.y, ph0, pl0);
    split2(v.z, v.w, ph1, pl1);
    *(uint2*)&s_hs_h[i] = make_uint2(ph0, ph1);
    *(uint2*)&s_hs_l[i] = make_uint2(pl0, pl1);
}

// ---------------------------------------------------------------------------
// Kernel 0b: tiled transpose of [K,N] weight -> single fp16 [N,K].
// ---------------------------------------------------------------------------
__global__ __launch_bounds__(256) void split_transpose(const float* __restrict__ in,
                                                       __half* __restrict__ oh,
                                                       int K, int N) {
    __shared__ float t[32][33];
    int nb = blockIdx.x * 32, kb = blockIdx.y * 32;
    int tx = threadIdx.x & 31, ty = threadIdx.x >> 5;
    #pragma unroll
    for (int i = 0; i < 4; i++) {
        int r = ty + i * 8;
        t[r][tx] = in[(size_t)(kb + r) * N + nb + tx];
    }
    __syncthreads();
    #pragma unroll
    for (int i = 0; i < 4; i++) {
        int r = ty + i * 8;
        oh[(size_t)(nb + r) * K + kb + tx] = __float2half_rn(t[tx][r]);
    }
}

// ---------------------------------------------------------------------------
// Kernel 1: QKV projection (unchanged from R11).
// ---------------------------------------------------------------------------
__global__ __launch_bounds__(256, 2) void qkv_gemm(const float* __restrict__ bias) {
    extern __shared__ __align__(16) char dynsmem[];
    const uint32_t smb = s2u(dynsmem);
    const int K = 1024;
    int tid = threadIdx.x, lane = tid & 31, wid = tid >> 5;
    int row0 = blockIdx.y * 128, col0 = blockIdx.x * 128;
    int mbase = (wid & 1) * 64, nbase = (wid >> 1) * 32;
    int srow = tid >> 1, sh = tid & 1;
    const __half* gAh = s_hs_h + (size_t)(row0 + srow) * K + sh * 32;
    const __half* gAl = s_hs_l + (size_t)(row0 + srow) * K + sh * 32;
    const __half* gB  = s_wa_h + (size_t)(col0 + srow) * K + sh * 32;
    uint32_t dA[4];
    #pragma unroll
    for (int i = 0; i < 4; i++) dA[i] = swz(srow, sh * 4 + i);

    float acc[4][4][4] = {};
    const int T = K / 64;

    #define QISSUE(t) do { uint32_t sb = smb + ((t) & 1) * SLOT_W; \
        _Pragma("unroll") for (int i = 0; i < 4; i++) { \
            cpa16(sb + dA[i],          gAh + (t) * 64 + i * 8); \
            cpa16(sb + 16384 + dA[i],  gAl + (t) * 64 + i * 8); \
            cpa16(sb + 32768 + dA[i],  gB  + (t) * 64 + i * 8); } } while (0)

    QISSUE(0); CP_COMMIT();
    for (int t = 0; t < T; t++) {
        CP_WAIT0();
        __syncthreads();
        if (t + 1 < T) QISSUE(t + 1);
        CP_COMMIT();
        cstage_w(smb + (t & 1) * SLOT_W, acc, mbase, nbase, lane);
    }
    #undef QISSUE

    #pragma unroll
    for (int i = 0; i < 4; i++) {
        #pragma unroll
        for (int j = 0; j < 4; j++) {
            int rr = row0 + mbase + i * 16 + (lane >> 2);
            int cc = col0 + nbase + j * 8 + (lane & 3) * 2;
            #pragma unroll
            for (int half = 0; half < 2; half++) {
                int r = rr + half * 8;
                int b = r >> 11, s = r & 2047;
                float v0 = acc[i][j][half * 2 + 0] + bias[cc];
                float v1 = acc[i][j][half * 2 + 1] + bias[cc + 1];
                int which = cc >> 10;
                int dcol = cc & 1023;
                int h = dcol >> 6, hd = dcol & 63;
                int bh = b * Hn + h;
                if (which == 0) {
                    uint32_t ph, pl; split2(v0, v1, ph, pl);
                    size_t idx = ((size_t)bh * Sn + s) * HDn + hd;
                    *(uint32_t*)&g_q_h[idx] = ph; *(uint32_t*)&g_q_l[idx] = pl;
                } else if (which == 1) {
                    size_t idx = ((size_t)bh * Sn + s) * HDn + hd;
                    *(uint32_t*)&g_k_h[idx] = pack2(v0, v1);
                } else {
                    uint32_t ph, pl; split2(v0, v1, ph, pl);
                    size_t i0 = ((size_t)bh * HDn + hd) * Sn + s;
                    size_t i1 = ((size_t)bh * HDn + hd + 1) * Sn + s;
                    ((uint16_t*)g_v_h)[i0] = (uint16_t)(ph & 0xffff);
                    ((uint16_t*)g_v_h)[i1] = (uint16_t)(ph >> 16);
                    ((uint16_t*)g_v_l)[i0] = (uint16_t)(pl & 0xffff);
                    ((uint16_t*)g_v_l)[i1] = (uint16_t)(pl >> 16);
                }
            }
        }
    }
}

// ---------------------------------------------------------------------------
// Kernel 2: raw scores (unchanged from R11).
// ---------------------------------------------------------------------------
__global__ __launch_bounds__(256, 2) void scores_kernel(const float* __restrict__ mask,
                                                        float* __restrict__ Wout) {
    extern __shared__ __align__(16) char dynsmem[];
    const uint32_t smb = s2u(dynsmem);
    int idx = blockIdx.x;
    int qb = (int)((sqrtf(8.0f * idx + 1.0f) - 1.0f) * 0.5f);
    while ((qb + 1) * (qb + 2) / 2 <= idx) qb++;
    while (qb * (qb + 1) / 2 > idx) qb--;
    int kb = idx - qb * (qb + 1) / 2;
    int bh = blockIdx.y;
    int bb = bh >> 4;
    int tid = threadIdx.x, lane = tid & 31, wid = tid >> 5;
    int row0 = qb * 128, col0 = kb * 128;
    int mbase = (wid & 1) * 64, nbase = (wid >> 1) * 32;
    int srow = tid >> 1, sh = tid & 1;
    const __half* gAh = g_q_h + ((size_t)bh * Sn + row0 + srow) * HDn + sh * 32;
    const __half* gAl = g_q_l + ((size_t)bh * Sn + row0 + srow) * HDn + sh * 32;
    const __half* gB  = g_k_h + ((size_t)bh * Sn + col0 + srow) * HDn + sh * 32;

    #pragma unroll
    for (int i = 0; i < 4; i++) {
        uint32_t d = swz(srow, sh * 4 + i);
        cpa16(smb + d,          gAh + i * 8);
        cpa16(smb + 16384 + d,  gAl + i * 8);
        cpa16(smb + 32768 + d,  gB  + i * 8);
    }
    CP_COMMIT();
    CP_WAIT0();
    __syncthreads();

    float acc[4][4][4] = {};
    cstage_w(smb, acc, mbase, nbase, lane);

    const float scale = 0.125f;
    #pragma unroll
    for (int i = 0; i < 4; i++) {
        #pragma unroll
        for (int j = 0; j < 4; j++) {
            int rr = row0 + mbase + i * 16 + (lane >> 2);
            int cc = col0 + nbase + j * 8 + (lane & 3) * 2;
            #pragma unroll
            for (int half = 0; half < 2; half++) {
                int r = rr + half * 8;
                float* orow = Wout + ((size_t)bh * Sn + r) * Sn;
                orow[cc]     = acc[i][j][half * 2 + 0] * scale + mask[bb * Sn + cc];
                orow[cc + 1] = acc[i][j][half * 2 + 1] * scale + mask[bb * Sn + cc + 1];
            }
        }
    }
}

// ---------------------------------------------------------------------------
// Kernel 3: FUSED softmax + AV. Per CTA: (qb, bh).
// Phase 1: warp-per-row online (max, sum) over the causal prefix.
// Phase 2: k32-stage pipeline — cp.async raw fp32 scores + split V; convert
//   raw -> normalized weights (write fp32 output + fp16 smem operand, masking
//   k>q to exact 0); ldsm + MMA. Zero tail written at the end.
// ---------------------------------------------------------------------------
__global__ __launch_bounds__(256, 3) void av_fused(float* __restrict__ Wm) {
    extern __shared__ __align__(16) char dynsmem[];
    const uint32_t smb = s2u(dynsmem);
    float* sm_m  = (float*)(dynsmem + AV_STATS);        // [128]
    float* sm_is = (float*)(dynsmem + AV_STATS) + 128;  // [128]
    int qb = gridDim.x - 1 - blockIdx.x;   // longest first
    int bh = blockIdx.y;
    int tid = threadIdx.x, lane = tid & 31, wid = tid >> 5;
    int row0 = qb * 128;
    int blockend = (qb + 1) * 128;
    float* wbase = Wm + (size_t)bh * Sn * Sn;

    // ---- Phase 1: stats (warp per row, 16 rows per warp) ----
    for (int it = 0; it < 16; it++) {
        int lr = wid + it * 8;           // local row
        int q = row0 + lr;
        int len = q + 1;
        float m[4] = {-1e30f, -1e30f, -1e30f, -1e30f};
        float s[4] = {0.f, 0.f, 0.f, 0.f};
        const float* rp = wbase + (size_t)q * Sn;
        for (int c = lane * 4; c < len; c += 128) {
            float4 v = *(const float4*)&rp[c];
            float xs[4] = {v.x, v.y, v.z, v.w};
            #pragma unroll
            for (int e = 0; e < 4; e++) {
                if (c + e < len) {
                    float x = xs[e];
                    if (x > m[e]) { s[e] = s[e] * __expf(m[e] - x) + 1.0f; m[e] = x; }
                    else s[e] += __expf(x - m[e]);
                }
            }
        }
        float M = m[0], S = s[0];
        #pragma unroll
        for (int e = 1; e < 4; e++) {
            float mm = fmaxf(M, m[e]);
            S = S * __expf(M - mm) + s[e] * __expf(m[e] - mm);
            M = mm;
        }
        #pragma unroll
        for (int o = 16; o > 0; o >>= 1) {
            float Mo = __shfl_xor_sync(0xffffffffu, M, o);
            float So = __shfl_xor_sync(0xffffffffu, S, o);
            float mm = fmaxf(M, Mo);
            S = S * __expf(M - mm) + So * __expf(Mo - mm);
            M = mm;
        }
        if (lane == 0) { sm_m[lr] = M; sm_is[lr] = 1.0f / S; }
    }
    __syncthreads();

    // ---- Phase 2: pipeline ----
    int mbase = (wid & 3) * 32, nbase = (wid >> 2) * 32;
    int srow = tid >> 1, sh = tid & 1;       // raw loader: 2 thr/row, 64B each
    int brow = tid >> 2, bq = tid & 3;       // B loader: 4 thr/row (64 rows), 16B
    int q_s = row0 + srow;
    const float* rawg = wbase + (size_t)q_s * Sn + sh * 16;
    const __half* gBh = g_v_h + ((size_t)bh * HDn + brow) * Sn + bq * 8;
    const __half* gBl = g_v_l + ((size_t)bh * HDn + brow) * Sn + bq * 8;
    uint32_t dRaw[4];
    #pragma unroll
    for (int i = 0; i < 4; i++) dRaw[i] = swz(srow, sh * 4 + i);
    uint32_t dBh = 16384u + swz64(brow, bq);
    uint32_t dBl = 20480u + swz64(brow, bq);
    float stat_m = sm_m[srow], stat_is = sm_is[srow];

    const int T = (qb + 1) * 4;   // k32 stages

    #define AVISSUE(t) do { uint32_t sb = smb + ((t) & 1) * AV_SLOT; \
        _Pragma("unroll") for (int i = 0; i < 4; i++) \
            cpa16(sb + dRaw[i], rawg + (t) * 32 + i * 4); \
        cpa16(sb + dBh, gBh + (t) * 32);  cpa16(sb + dBl, gBl + (t) * 32); } while (0)

    float acc[2][4][4] = {};

    AVISSUE(0); CP_COMMIT();
    for (int t = 0; t < T; t++) {
        CP_WAIT0();
        __syncthreads();
        if (t + 1 < T) AVISSUE(t + 1);
        CP_COMMIT();
        uint32_t sb = smb + (t & 1) * AV_SLOT;

        // convert raw -> fp16 A region + write normalized fp32 weights
        {
            float* orow = wbase + (size_t)q_s * Sn;
            #pragma unroll
            for (int i = 0; i < 4; i++) {
                float4 v = *(const float4*)(dynsmem + ((t & 1) * AV_SLOT) + swz(srow, sh * 4 + i));
                int k0 = t * 32 + sh * 16 + i * 4;
                float4 w;
                w.x = (k0     <= q_s) ? __expf(v.x - stat_m) * stat_is : 0.0f;
                w.y = (k0 + 1 <= q_s) ? __expf(v.y - stat_m) * stat_is : 0.0f;
                w.z = (k0 + 2 <= q_s) ? __expf(v.z - stat_m) * stat_is : 0.0f;
                w.w = (k0 + 3 <= q_s) ? __expf(v.w - stat_m) * stat_is : 0.0f;
                *(float4*)&orow[k0] = w;
                uint2 p = make_uint2(pack2(w.x, w.y), pack2(w.z, w.w));
                int c16 = sh * 2 + (i >> 1);
                *(uint2*)(dynsmem + AV_A16 + swz64(srow, c16) + (i & 1) * 8) = p;
            }
        }
        __syncthreads();

        // MMA: warp 32m x 32n, 2 k16 steps
        #pragma unroll
        for (int kk = 0; kk < 2; kk++) {
            uint32_t bhf[4][2], blf[4][2];
            #pragma unroll
            for (int jg = 0; jg < 2; jg++) {
                int br = nbase + jg * 16 + (lane & 7) + ((lane >> 4) << 3);
                int bch = kk * 2 + ((lane >> 3) & 1);
                uint32_t r0, r1, r2, r3;
                ldsm4(r0, r1, r2, r3, sb + 16384u + swz64(br, bch));
                bhf[jg * 2][0] = r0; bhf[jg * 2][1] = r1;
                bhf[jg * 2 + 1][0] = r2; bhf[jg * 2 + 1][1] = r3;
                ldsm4(r0, r1, r2, r3, sb + 20480u + swz64(br, bch));
                blf[jg * 2][0] = r0; blf[jg * 2][1] = r1;
                blf[jg * 2 + 1][0] = r2; blf[jg * 2 + 1][1] = r3;
            }
            #pragma unroll
            for (int i = 0; i < 2; i++) {
                int ar = mbase + i * 16 + (lane & 15);
                int ach = kk * 2 + (lane >> 4);
                uint32_t ah[4];
                ldsm4(ah[0], ah[1], ah[2], ah[3],
                      smb + AV_A16 + swz64(ar, ach));
                #pragma unroll
                for (int j = 0; j < 4; j++) {
                    MMAF(acc[i][j], ah, bhf[j]);
                    MMAF(acc[i][j], ah, blf[j]);
                }
            }
        }
    }
    #undef AVISSUE

    // zero tail of weights rows [blockend, Sn)
    int tail = Sn - blockend;
    if (tail > 0) {
        for (int e = tid * 4; e < 128 * tail; e += 1024) {
            int r = e / tail;
            int c = blockend + (e - r * tail);
            *(float4*)&wbase[(size_t)(row0 + r) * Sn + c] =
                make_float4(0.f, 0.f, 0.f, 0.f);
        }
    }

    // epilogue: att split
    #pragma unroll
    for (int i = 0; i < 2; i++) {
        #pragma unroll
        for (int j = 0; j < 4; j++) {
            int rr = row0 + mbase + i * 16 + (lane >> 2);
            int cc = nbase + j * 8 + (lane & 3) * 2;
            #pragma unroll
            for (int half = 0; half < 2; half++) {
                int r = rr + half * 8;
                uint32_t ph, pl;
                split2(acc[i][j][half * 2 + 0], acc[i][j][half * 2 + 1], ph, pl);
                size_t idx = ((size_t)bh * Sn + r) * HDn + cc;
                *(uint32_t*)&g_att_h[idx] = ph;
                *(uint32_t*)&g_att_l[idx] = pl;
            }
        }
    }
}

// ---------------------------------------------------------------------------
// Kernel 5: output projection (unchanged from R11).
// ---------------------------------------------------------------------------
__global__ __launch_bounds__(256, 2) void proj_gemm(const float* __restrict__ bias,
                                                    float* __restrict__ out) {
    extern __shared__ __align__(16) char dynsmem[];
    const uint32_t smb = s2u(dynsmem);
    const int K = 1024, N = 1024;
    int tid = threadIdx.x, lane = tid & 31, wid = tid >> 5;
    int row0 = blockIdx.y * 128, col0 = blockIdx.x * 128;
    int mbase = (wid & 1) * 64, nbase = (wid >> 1) * 32;
    int srow = tid >> 1, sh = tid & 1;
    int arow = row0 + srow;
    int ab = arow >> 11, as = arow & 2047;
    size_t abase = (((size_t)ab * Hn) * Sn + as) * HDn + sh * 32;
    const __half* gB = s_wp_h + (size_t)(col0 + srow) * K + sh * 32;
    uint32_t dA[4];
    #pragma unroll
    for (int i = 0; i < 4; i++) dA[i] = swz(srow, sh * 4 + i);

    float acc[4][4][4] = {};
    const int T = K / 64;

    #define PISSUE(t) do { uint32_t sb = smb + ((t) & 1) * SLOT_W; \
        size_t so = abase + (size_t)(t) * Sn * HDn; \
        _Pragma("unroll") for (int i = 0; i < 4; i++) { \
            cpa16(sb + dA[i],          g_att_h + so + i * 8); \
            cpa16(sb + 16384 + dA[i],  g_att_l + so + i * 8); \
            cpa16(sb + 32768 + dA[i],  gB + (t) * 64 + i * 8); } } while (0)

    PISSUE(0); CP_COMMIT();
    for (int t = 0; t < T; t++) {
        CP_WAIT0();
        __syncthreads();
        if (t + 1 < T) PISSUE(t + 1);
        CP_COMMIT();
        cstage_w(smb + (t & 1) * SLOT_W, acc, mbase, nbase, lane);
    }
    #undef PISSUE

    #pragma unroll
    for (int i = 0; i < 4; i++) {
        #pragma unroll
        for (int j = 0; j < 4; j++) {
            int rr = row0 + mbase + i * 16 + (lane >> 2);
            int cc = col0 + nbase + j * 8 + (lane & 3) * 2;
            #pragma unroll
            for (int half = 0; half < 2; half++) {
                int r = rr + half * 8;
                out[(size_t)r * N + cc]     = acc[i][j][half * 2 + 0] + bias[cc];
                out[(size_t)r * N + cc + 1] = acc[i][j][half * 2 + 1] + bias[cc + 1];
            }
        }
    }
}

// ---------------------------------------------------------------------------
extern "C" void kernel_launch(void* const* d_in, const int* in_sizes, int n_in,
                              void* d_out, int out_size) {
    (void)in_sizes; (void)n_in; (void)out_size;
    const float* hs     = (const float*)d_in[0];
    const float* mask   = (const float*)d_in[1];
    const float* w_attn = (const float*)d_in[2];
    const float* b_attn = (const float*)d_in[3];
    const float* w_proj = (const float*)d_in[4];
    const float* b_proj = (const float*)d_in[5];

    float* attn_out = (float*)d_out;                          // [B,S,D]
    float* weights  = (float*)d_out + (size_t)Bn * Sn * Dn;   // [B,H,S,S]

    cudaFuncSetAttribute(qkv_gemm,      cudaFuncAttributeMaxDynamicSharedMemorySize, SMEM_W);
    cudaFuncSetAttribute(scores_kernel, cudaFuncAttributeMaxDynamicSharedMemorySize, SMEM_SC);
    cudaFuncSetAttribute(av_fused,      cudaFuncAttributeMaxDynamicSharedMemorySize, SMEM_AVF);
    cudaFuncSetAttribute(proj_gemm,     cudaFuncAttributeMaxDynamicSharedMemorySize, SMEM_W);

    __half *wa_h, *wp_h;
    cudaGetSymbolAddress((void**)&wa_h, s_wa_h);
    cudaGetSymbolAddress((void**)&wp_h, s_wp_h);

    split_hs<<<BSn * Dn / 1024, 256>>>(hs);
    split_transpose<<<dim3(N3D / 32, Dn / 32), 256>>>(w_attn, wa_h, Dn, N3D);
    split_transpose<<<dim3(Dn / 32, Dn / 32), 256>>>(w_proj, wp_h, Dn, Dn);
    qkv_gemm<<<dim3(N3D / 128, BSn / 128), 256, SMEM_W>>>(b_attn);
    scores_kernel<<<dim3(136, Bn * Hn), 256, SMEM_SC>>>(mask, weights);
    av_fused<<<dim3(Sn / 128, Bn * Hn), 256, SMEM_AVF>>>(weights);
    proj_gemm<<<dim3(Dn / 128, BSn / 128), 256, SMEM_W>>>(b_proj, attn_out);
}

// round 13
// speedup vs baseline: 1.6562x; 1.6562x over previous
#include <cuda_runtime.h>
#include <cuda_fp16.h>
#include <math.h>
#include <stdint.h>

#define Bn 2
#define Sn 2048
#define Dn 1024
#define Hn 16
#define HDn 64
#define BSn (Bn*Sn)      // 4096
#define N3D (3*Dn)       // 3072
#define NQKV (Bn*Hn*Sn*HDn)

// single-single wide stage (128m x 128n, k64): A 16KB | B 16KB = 32KB
#define SLOT_SS 32768
#define SMEM_SS (2*SLOT_SS)   // 65536 -> 2+ CTAs/SM
// scores single-shot (q split): Ah 16KB | Al 16KB | B 16KB
#define SMEM_SC 49152
// av single-single stage (128m x 64n, k64): A 16KB | B 8KB = 24KB
#define SLOT_AV 24576
#define SMEM_AV (2*SLOT_AV)   // 49152 -> 3 CTAs/SM

// ---------------- fp16 scratch (device globals) ----------------
__device__ __half s_hs_h[BSn*Dn];                    // hidden states single
__device__ __half s_wa_h[N3D*Dn];                    // w_attn^T single
__device__ __half s_wp_h[Dn*Dn];                     // w_proj^T single
__device__ __half g_q_h[NQKV], g_q_l[NQKV];          // q split   [bh][s][hd]
__device__ __half g_k_h[NQKV];                       // k single  [bh][s][hd]
__device__ __half g_v_h[NQKV];                       // v single  [bh][hd][s]
__device__ __half g_att_h[NQKV];                     // att single [bh][s][hd]
__device__ __half g_w_h[(size_t)Bn*Hn*Sn*Sn];        // weights single

// ---------------- helpers ----------------
__device__ __forceinline__ uint32_t s2u(const void* p) {
    return (uint32_t)__cvta_generic_to_shared(p);
}
__device__ __forceinline__ void ldsm4(uint32_t& r0, uint32_t& r1, uint32_t& r2,
                                      uint32_t& r3, uint32_t a) {
    asm volatile("ldmatrix.sync.aligned.m8n8.x4.shared.b16 {%0,%1,%2,%3},[%4];"
                 : "=r"(r0), "=r"(r1), "=r"(r2), "=r"(r3) : "r"(a));
}
#define MMAF(c, a, b) asm volatile( \
    "mma.sync.aligned.m16n8k16.row.col.f32.f16.f16.f32 " \
    "{%0,%1,%2,%3},{%4,%5,%6,%7},{%8,%9},{%0,%1,%2,%3};" \
    : "+f"((c)[0]), "+f"((c)[1]), "+f"((c)[2]), "+f"((c)[3]) \
    : "r"((a)[0]), "r"((a)[1]), "r"((a)[2]), "r"((a)[3]), "r"((b)[0]), "r"((b)[1]))

__device__ __forceinline__ void cpa16(uint32_t dst, const void* src) {
    asm volatile("cp.async.cg.shared.global [%0], [%1], 16;" :: "r"(dst), "l"(src));
}
#define CP_COMMIT() asm volatile("cp.async.commit_group;")
#define CP_WAIT0()  asm volatile("cp.async.wait_group 0;")

// byte offset of 16B chunk c (0..7) in swizzled 128B row
__device__ __forceinline__ uint32_t swz(int row, int c) {
    return (uint32_t)row * 128u + (uint32_t)((c ^ (row & 7)) << 4);
}

__device__ __forceinline__ void split2(float x, float y, uint32_t& ph, uint32_t& pl) {
    __half2 h2 = __floats2half2_rn(x, y);
    ph = *reinterpret_cast<uint32_t*>(&h2);
    __half2 l2 = __floats2half2_rn(x - __half2float(__low2half(h2)),
                                   y - __half2float(__high2half(h2)));
    pl = *reinterpret_cast<uint32_t*>(&l2);
}
__device__ __forceinline__ uint32_t pack2(float x, float y) {
    __half2 h2 = __floats2half2_rn(x, y);
    return *reinterpret_cast<uint32_t*>(&h2);
}

// single-single wide stage (k64): A @0 (128 rows), B @16384 (128 rows).
// warp grid 2m x 4n: warp tile 64m x 32n; acc[4][4][4].
__device__ __forceinline__ void cstage_ss(uint32_t sb, float acc[4][4][4],
                                          int mbase, int nbase, int lane) {
    #pragma unroll
    for (int kk = 0; kk < 4; kk++) {
        uint32_t bf[4][2];
        #pragma unroll
        for (int jg = 0; jg < 2; jg++) {
            int brow = nbase + jg * 16 + (lane & 7) + ((lane >> 4) << 3);
            int bch = kk * 2 + ((lane >> 3) & 1);
            uint32_t r0, r1, r2, r3;
            ldsm4(r0, r1, r2, r3, sb + 16384u + swz(brow, bch));
            bf[jg * 2][0] = r0; bf[jg * 2][1] = r1;
            bf[jg * 2 + 1][0] = r2; bf[jg * 2 + 1][1] = r3;
        }
        #pragma unroll
        for (int i = 0; i < 4; i++) {
            int arow = mbase + i * 16 + (lane & 15);
            int ach = kk * 2 + (lane >> 4);
            uint32_t ah[4];
            ldsm4(ah[0], ah[1], ah[2], ah[3], sb + swz(arow, ach));
            #pragma unroll
            for (int j = 0; j < 4; j++) MMAF(acc[i][j], ah, bf[j]);
        }
    }
}

// scores stage (k64, single shot): split A (Ah @0, Al @16384), B @32768.
__device__ __forceinline__ void cstage_sc(uint32_t sb, float acc[4][4][4],
                                          int mbase, int nbase, int lane) {
    #pragma unroll
    for (int kk = 0; kk < 4; kk++) {
        uint32_t bf[4][2];
        #pragma unroll
        for (int jg = 0; jg < 2; jg++) {
            int brow = nbase + jg * 16 + (lane & 7) + ((lane >> 4) << 3);
            int bch = kk * 2 + ((lane >> 3) & 1);
            uint32_t r0, r1, r2, r3;
            ldsm4(r0, r1, r2, r3, sb + 32768u + swz(brow, bch));
            bf[jg * 2][0] = r0; bf[jg * 2][1] = r1;
            bf[jg * 2 + 1][0] = r2; bf[jg * 2 + 1][1] = r3;
        }
        #pragma unroll
        for (int i = 0; i < 4; i++) {
            int arow = mbase + i * 16 + (lane & 15);
            int ach = kk * 2 + (lane >> 4);
            uint32_t ah[4], al[4];
            ldsm4(ah[0], ah[1], ah[2], ah[3], sb + swz(arow, ach));
            ldsm4(al[0], al[1], al[2], al[3], sb + 16384u + swz(arow, ach));
            #pragma unroll
            for (int j = 0; j < 4; j++) {
                MMAF(acc[i][j], ah, bf[j]);
                MMAF(acc[i][j], al, bf[j]);
            }
        }
    }
}

// av stage (k64): A @0 (128 rows), B @16384 (64 rows).
// warp grid 4m x 2n: warp tile 32m x 32n; acc[2][4][4].
__device__ __forceinline__ void cstage_av(uint32_t sb, float acc[2][4][4],
                                          int mbase, int nbase, int lane) {
    #pragma unroll
    for (int kk = 0; kk < 4; kk++) {
        uint32_t bf[4][2];
        #pragma unroll
        for (int jg = 0; jg < 2; jg++) {
            int brow = nbase + jg * 16 + (lane & 7) + ((lane >> 4) << 3);
            int bch = kk * 2 + ((lane >> 3) & 1);
            uint32_t r0, r1, r2, r3;
            ldsm4(r0, r1, r2, r3, sb + 16384u + swz(brow, bch));
            bf[jg * 2][0] = r0; bf[jg * 2][1] = r1;
            bf[jg * 2 + 1][0] = r2; bf[jg * 2 + 1][1] = r3;
        }
        #pragma unroll
        for (int i = 0; i < 2; i++) {
            int arow = mbase + i * 16 + (lane & 15);
            int ach = kk * 2 + (lane >> 4);
            uint32_t ah[4];
            ldsm4(ah[0], ah[1], ah[2], ah[3], sb + swz(arow, ach));
            #pragma unroll
            for (int j = 0; j < 4; j++) MMAF(acc[i][j], ah, bf[j]);
        }
    }
}

// ---------------------------------------------------------------------------
// Kernel 0a: hidden states -> single fp16.
// ---------------------------------------------------------------------------
__global__ __launch_bounds__(256) void split_hs(const float* __restrict__ hs) {
    int i = (blockIdx.x * 256 + threadIdx.x) * 4;
    float4 v = *(const float4*)&hs[i];
    *(uint2*)&s_hs_h[i] = make_uint2(pack2(v.x, v.y), pack2(v.z, v.w));
}

// ---------------------------------------------------------------------------
// Kernel 0b: tiled transpose of [K,N] weight -> single fp16 [N,K].
// ---------------------------------------------------------------------------
__global__ __launch_bounds__(256) void split_transpose(const float* __restrict__ in,
                                                       __half* __restrict__ oh,
                                                       int K, int N) {
    __shared__ float t[32][33];
    int nb = blockIdx.x * 32, kb = blockIdx.y * 32;
    int tx = threadIdx.x & 31, ty = threadIdx.x >> 5;
    #pragma unroll
    for (int i = 0; i < 4; i++) {
        int r = ty + i * 8;
        t[r][tx] = in[(size_t)(kb + r) * N + nb + tx];
    }
    __syncthreads();
    #pragma unroll
    for (int i = 0; i < 4; i++) {
        int r = ty + i * 8;
        oh[(size_t)(nb + r) * K + kb + tx] = __float2half_rn(t[tx][r]);
    }
}

// ---------------------------------------------------------------------------
// Kernel 1: QKV projection. 128m x 128n, warp 64x32, k64 x 16 stages, 1-term.
// ---------------------------------------------------------------------------
__global__ __launch_bounds__(256, 2) void qkv_gemm(const float* __restrict__ bias) {
    extern __shared__ __align__(16) char dynsmem[];
    const uint32_t smb = s2u(dynsmem);
    const int K = 1024;
    int tid = threadIdx.x, lane = tid & 31, wid = tid >> 5;
    int row0 = blockIdx.y * 128, col0 = blockIdx.x * 128;
    int mbase = (wid & 1) * 64, nbase = (wid >> 1) * 32;
    int srow = tid >> 1, sh = tid & 1;
    const __half* gA = s_hs_h + (size_t)(row0 + srow) * K + sh * 32;
    const __half* gB = s_wa_h + (size_t)(col0 + srow) * K + sh * 32;
    uint32_t dA[4];
    #pragma unroll
    for (int i = 0; i < 4; i++) dA[i] = swz(srow, sh * 4 + i);

    float acc[4][4][4] = {};
    const int T = K / 64;

    #define QISSUE(t) do { uint32_t sb = smb + ((t) & 1) * SLOT_SS; \
        _Pragma("unroll") for (int i = 0; i < 4; i++) { \
            cpa16(sb + dA[i],          gA + (t) * 64 + i * 8); \
            cpa16(sb + 16384 + dA[i],  gB + (t) * 64 + i * 8); } } while (0)

    QISSUE(0); CP_COMMIT();
    for (int t = 0; t < T; t++) {
        CP_WAIT0();
        __syncthreads();
        if (t + 1 < T) QISSUE(t + 1);
        CP_COMMIT();
        cstage_ss(smb + (t & 1) * SLOT_SS, acc, mbase, nbase, lane);
    }
    #undef QISSUE

    #pragma unroll
    for (int i = 0; i < 4; i++) {
        #pragma unroll
        for (int j = 0; j < 4; j++) {
            int rr = row0 + mbase + i * 16 + (lane >> 2);
            int cc = col0 + nbase + j * 8 + (lane & 3) * 2;
            #pragma unroll
            for (int half = 0; half < 2; half++) {
                int r = rr + half * 8;
                int b = r >> 11, s = r & 2047;
                float v0 = acc[i][j][half * 2 + 0] + bias[cc];
                float v1 = acc[i][j][half * 2 + 1] + bias[cc + 1];
                int which = cc >> 10;
                int dcol = cc & 1023;
                int h = dcol >> 6, hd = dcol & 63;
                int bh = b * Hn + h;
                if (which == 0) {          // q: split (protects exp path)
                    uint32_t ph, pl; split2(v0, v1, ph, pl);
                    size_t idx = ((size_t)bh * Sn + s) * HDn + hd;
                    *(uint32_t*)&g_q_h[idx] = ph; *(uint32_t*)&g_q_l[idx] = pl;
                } else if (which == 1) {   // k: single
                    size_t idx = ((size_t)bh * Sn + s) * HDn + hd;
                    *(uint32_t*)&g_k_h[idx] = pack2(v0, v1);
                } else {                   // v: single, transposed [bh][hd][s]
                    uint32_t ph = pack2(v0, v1);
                    size_t i0 = ((size_t)bh * HDn + hd) * Sn + s;
                    size_t i1 = ((size_t)bh * HDn + hd + 1) * Sn + s;
                    ((uint16_t*)g_v_h)[i0] = (uint16_t)(ph & 0xffff);
                    ((uint16_t*)g_v_h)[i1] = (uint16_t)(ph >> 16);
                }
            }
        }
    }
}

// ---------------------------------------------------------------------------
// Kernel 2: raw scores, lower-tri 128q x 128k tiles, K=64 single-shot.
// A = q split (2-term), B = k single. (unchanged from R11)
// ---------------------------------------------------------------------------
__global__ __launch_bounds__(256, 2) void scores_kernel(const float* __restrict__ mask,
                                                        float* __restrict__ Wout) {
    extern __shared__ __align__(16) char dynsmem[];
    const uint32_t smb = s2u(dynsmem);
    int idx = blockIdx.x;
    int qb = (int)((sqrtf(8.0f * idx + 1.0f) - 1.0f) * 0.5f);
    while ((qb + 1) * (qb + 2) / 2 <= idx) qb++;
    while (qb * (qb + 1) / 2 > idx) qb--;
    int kb = idx - qb * (qb + 1) / 2;
    int bh = blockIdx.y;
    int bb = bh >> 4;
    int tid = threadIdx.x, lane = tid & 31, wid = tid >> 5;
    int row0 = qb * 128, col0 = kb * 128;
    int mbase = (wid & 1) * 64, nbase = (wid >> 1) * 32;
    int srow = tid >> 1, sh = tid & 1;
    const __half* gAh = g_q_h + ((size_t)bh * Sn + row0 + srow) * HDn + sh * 32;
    const __half* gAl = g_q_l + ((size_t)bh * Sn + row0 + srow) * HDn + sh * 32;
    const __half* gB  = g_k_h + ((size_t)bh * Sn + col0 + srow) * HDn + sh * 32;

    #pragma unroll
    for (int i = 0; i < 4; i++) {
        uint32_t d = swz(srow, sh * 4 + i);
        cpa16(smb + d,          gAh + i * 8);
        cpa16(smb + 16384 + d,  gAl + i * 8);
        cpa16(smb + 32768 + d,  gB  + i * 8);
    }
    CP_COMMIT();
    CP_WAIT0();
    __syncthreads();

    float acc[4][4][4] = {};
    cstage_sc(smb, acc, mbase, nbase, lane);

    const float scale = 0.125f;
    #pragma unroll
    for (int i = 0; i < 4; i++) {
        #pragma unroll
        for (int j = 0; j < 4; j++) {
            int rr = row0 + mbase + i * 16 + (lane >> 2);
            int cc = col0 + nbase + j * 8 + (lane & 3) * 2;
            #pragma unroll
            for (int half = 0; half < 2; half++) {
                int r = rr + half * 8;
                float* orow = Wout + ((size_t)bh * Sn + r) * Sn;
                orow[cc]     = acc[i][j][half * 2 + 0] * scale + mask[bb * Sn + cc];
                orow[cc + 1] = acc[i][j][half * 2 + 1] * scale + mask[bb * Sn + cc + 1];
            }
        }
    }
}

// ---------------------------------------------------------------------------
// Kernel 3: row softmax; fp32 weights (output) + fp16 single band. (R11)
// ---------------------------------------------------------------------------
__global__ __launch_bounds__(256) void softmax_kernel(float* __restrict__ Wm) {
    __shared__ float buf[Sn];
    __shared__ float red[8];
    int row = blockIdx.x;
    int q = row & (Sn - 1);
    int len = q + 1;
    int blockend = ((q >> 7) + 1) << 7;
    float* wrow = Wm + (size_t)row * Sn;
    size_t wb = (size_t)row * Sn;
    int tid = threadIdx.x;
    int lane = tid & 31, warp = tid >> 5;

    float mx = -1e30f;
    for (int c = tid * 4; c < blockend; c += 1024) {
        float4 v = *(const float4*)&wrow[c];
        *(float4*)&buf[c] = v;
        if (c + 3 < len) {
            mx = fmaxf(mx, fmaxf(fmaxf(v.x, v.y), fmaxf(v.z, v.w)));
        } else {
            if (c     < len) mx = fmaxf(mx, v.x);
            if (c + 1 < len) mx = fmaxf(mx, v.y);
            if (c + 2 < len) mx = fmaxf(mx, v.z);
            if (c + 3 < len) mx = fmaxf(mx, v.w);
        }
    }
    #pragma unroll
    for (int o = 16; o > 0; o >>= 1) mx = fmaxf(mx, __shfl_xor_sync(0xffffffffu, mx, o));
    if (lane == 0) red[warp] = mx;
    __syncthreads();
    if (tid < 32) {
        float t = (tid < 8) ? red[tid] : -1e30f;
        #pragma unroll
        for (int o = 4; o > 0; o >>= 1) t = fmaxf(t, __shfl_xor_sync(0xffffffffu, t, o));
        if (tid == 0) red[0] = t;
    }
    __syncthreads();
    mx = red[0];
    __syncthreads();

    float sum = 0.0f;
    for (int c = tid * 4; c < blockend; c += 1024) {
        float4 v = *(const float4*)&buf[c];
        float e0 = (c     < len) ? __expf(v.x - mx) : 0.0f;
        float e1 = (c + 1 < len) ? __expf(v.y - mx) : 0.0f;
        float e2 = (c + 2 < len) ? __expf(v.z - mx) : 0.0f;
        float e3 = (c + 3 < len) ? __expf(v.w - mx) : 0.0f;
        sum += (e0 + e1) + (e2 + e3);
        *(float4*)&buf[c] = make_float4(e0, e1, e2, e3);
    }
    #pragma unroll
    for (int o = 16; o > 0; o >>= 1) sum += __shfl_xor_sync(0xffffffffu, sum, o);
    if (lane == 0) red[warp] = sum;
    __syncthreads();
    if (tid < 32) {
        float t = (tid < 8) ? red[tid] : 0.0f;
        #pragma unroll
        for (int o = 4; o > 0; o >>= 1) t += __shfl_xor_sync(0xffffffffu, t, o);
        if (tid == 0) red[0] = t;
    }
    __syncthreads();
    float inv = 1.0f / red[0];

    for (int c = tid * 4; c < blockend; c += 1024) {
        float4 v = *(const float4*)&buf[c];
        v.x *= inv; v.y *= inv; v.z *= inv; v.w *= inv;
        *(float4*)&wrow[c] = v;
        *(uint2*)&g_w_h[wb + c] = make_uint2(pack2(v.x, v.y), pack2(v.z, v.w));
    }
    for (int c = blockend + tid * 4; c < Sn; c += 1024)
        *(float4*)&wrow[c] = make_float4(0.f, 0.f, 0.f, 0.f);
}

// ---------------------------------------------------------------------------
// Kernel 4: attn_heads = weights @ V. 128m x 64n, warp 32x32, k64, 1-term.
// ---------------------------------------------------------------------------
__global__ __launch_bounds__(256, 3) void av_kernel() {
    extern __shared__ __align__(16) char dynsmem[];
    const uint32_t smb = s2u(dynsmem);
    int qb = gridDim.x - 1 - blockIdx.x;   // longest first
    int bh = blockIdx.y;
    int tid = threadIdx.x, lane = tid & 31, wid = tid >> 5;
    int row0 = qb * 128;
    int mbase = (wid & 3) * 32, nbase = (wid >> 2) * 32;
    int srow = tid >> 1, sh = tid & 1;
    int brow = tid >> 2, bq = tid & 3;
    const __half* gA = g_w_h + (size_t)bh * Sn * Sn + (size_t)(row0 + srow) * Sn + sh * 32;
    const __half* gB = g_v_h + ((size_t)bh * HDn + brow) * Sn + bq * 16;
    uint32_t dA[4];
    #pragma unroll
    for (int i = 0; i < 4; i++) dA[i] = swz(srow, sh * 4 + i);
    uint32_t dB0 = 16384u + swz(brow, bq * 2), dB1 = 16384u + swz(brow, bq * 2 + 1);

    float acc[2][4][4] = {};
    const int T = (qb + 1) * 2;

    #define AISSUE(t) do { uint32_t sb = smb + ((t) & 1) * SLOT_AV; \
        _Pragma("unroll") for (int i = 0; i < 4; i++) \
            cpa16(sb + dA[i], gA + (t) * 64 + i * 8); \
        cpa16(sb + dB0, gB + (t) * 64);  cpa16(sb + dB1, gB + (t) * 64 + 8); } while (0)

    AISSUE(0); CP_COMMIT();
    for (int t = 0; t < T; t++) {
        CP_WAIT0();
        __syncthreads();
        if (t + 1 < T) AISSUE(t + 1);
        CP_COMMIT();
        cstage_av(smb + (t & 1) * SLOT_AV, acc, mbase, nbase, lane);
    }
    #undef AISSUE

    #pragma unroll
    for (int i = 0; i < 2; i++) {
        #pragma unroll
        for (int j = 0; j < 4; j++) {
            int rr = row0 + mbase + i * 16 + (lane >> 2);
            int cc = nbase + j * 8 + (lane & 3) * 2;
            #pragma unroll
            for (int half = 0; half < 2; half++) {
                int r = rr + half * 8;
                size_t idx = ((size_t)bh * Sn + r) * HDn + cc;
                *(uint32_t*)&g_att_h[idx] =
                    pack2(acc[i][j][half * 2 + 0], acc[i][j][half * 2 + 1]);
            }
        }
    }
}

// ---------------------------------------------------------------------------
// Kernel 5: output projection. 128m x 128n, warp 64x32, k64, 1-term.
// A = att single (head-transpose), B = wp single.
// ---------------------------------------------------------------------------
__global__ __launch_bounds__(256, 2) void proj_gemm(const float* __restrict__ bias,
                                                    float* __restrict__ out) {
    extern __shared__ __align__(16) char dynsmem[];
    const uint32_t smb = s2u(dynsmem);
    const int K = 1024, N = 1024;
    int tid = threadIdx.x, lane = tid & 31, wid = tid >> 5;
    int row0 = blockIdx.y * 128, col0 = blockIdx.x * 128;
    int mbase = (wid & 1) * 64, nbase = (wid >> 1) * 32;
    int srow = tid >> 1, sh = tid & 1;
    int arow = row0 + srow;
    int ab = arow >> 11, as = arow & 2047;
    size_t abase = (((size_t)ab * Hn) * Sn + as) * HDn + sh * 32;
    const __half* gB = s_wp_h + (size_t)(col0 + srow) * K + sh * 32;
    uint32_t dA[4];
    #pragma unroll
    for (int i = 0; i < 4; i++) dA[i] = swz(srow, sh * 4 + i);

    float acc[4][4][4] = {};
    const int T = K / 64;   // stage t = head t

    #define PISSUE(t) do { uint32_t sb = smb + ((t) & 1) * SLOT_SS; \
        size_t so = abase + (size_t)(t) * Sn * HDn; \
        _Pragma("unroll") for (int i = 0; i < 4; i++) { \
            cpa16(sb + dA[i],          g_att_h + so + i * 8); \
            cpa16(sb + 16384 + dA[i],  gB + (t) * 64 + i * 8); } } while (0)

    PISSUE(0); CP_COMMIT();
    for (int t = 0; t < T; t++) {
        CP_WAIT0();
        __syncthreads();
        if (t + 1 < T) PISSUE(t + 1);
        CP_COMMIT();
        cstage_ss(smb + (t & 1) * SLOT_SS, acc, mbase, nbase, lane);
    }
    #undef PISSUE

    #pragma unroll
    for (int i = 0; i < 4; i++) {
        #pragma unroll
        for (int j = 0; j < 4; j++) {
            int rr = row0 + mbase + i * 16 + (lane >> 2);
            int cc = col0 + nbase + j * 8 + (lane & 3) * 2;
            #pragma unroll
            for (int half = 0; half < 2; half++) {
                int r = rr + half * 8;
                out[(size_t)r * N + cc]     = acc[i][j][half * 2 + 0] + bias[cc];
                out[(size_t)r * N + cc + 1] = acc[i][j][half * 2 + 1] + bias[cc + 1];
            }
        }
    }
}

// ---------------------------------------------------------------------------
extern "C" void kernel_launch(void* const* d_in, const int* in_sizes, int n_in,
                              void* d_out, int out_size) {
    (void)in_sizes; (void)n_in; (void)out_size;
    const float* hs     = (const float*)d_in[0];
    const float* mask   = (const float*)d_in[1];
    const float* w_attn = (const float*)d_in[2];
    const float* b_attn = (const float*)d_in[3];
    const float* w_proj = (const float*)d_in[4];
    const float* b_proj = (const float*)d_in[5];

    float* attn_out = (float*)d_out;                          // [B,S,D]
    float* weights  = (float*)d_out + (size_t)Bn * Sn * Dn;   // [B,H,S,S]

    cudaFuncSetAttribute(qkv_gemm,      cudaFuncAttributeMaxDynamicSharedMemorySize, SMEM_SS);
    cudaFuncSetAttribute(scores_kernel, cudaFuncAttributeMaxDynamicSharedMemorySize, SMEM_SC);
    cudaFuncSetAttribute(av_kernel,     cudaFuncAttributeMaxDynamicSharedMemorySize, SMEM_AV);
    cudaFuncSetAttribute(proj_gemm,     cudaFuncAttributeMaxDynamicSharedMemorySize, SMEM_SS);

    __half *wa_h, *wp_h;
    cudaGetSymbolAddress((void**)&wa_h, s_wa_h);
    cudaGetSymbolAddress((void**)&wp_h, s_wp_h);

    split_hs<<<BSn * Dn / 1024, 256>>>(hs);
    split_transpose<<<dim3(N3D / 32, Dn / 32), 256>>>(w_attn, wa_h, Dn, N3D);
    split_transpose<<<dim3(Dn / 32, Dn / 32), 256>>>(w_proj, wp_h, Dn, Dn);
    qkv_gemm<<<dim3(N3D / 128, BSn / 128), 256, SMEM_SS>>>(b_attn);
    scores_kernel<<<dim3(136, Bn * Hn), 256, SMEM_SC>>>(mask, weights);
    softmax_kernel<<<dim3(Bn * Hn * Sn), 256>>>(weights);
    av_kernel<<<dim3(Sn / 128, Bn * Hn), 256, SMEM_AV>>>();
    proj_gemm<<<dim3(Dn / 128, BSn / 128), 256, SMEM_SS>>>(b_proj, attn_out);
}